// round 1
// baseline (speedup 1.0000x reference)
#include <cuda_runtime.h>

#define TILE_E 128
#define THREADS 128
#define D 64
#define BK 32

// dynamic smem layout (floats):
//  sH : [64][128]   @ 0      (8192)  h1 transposed (k-major) for layer2
//  sA : [32][128]   @ 8192   (4096)  input chunk, transposed
//  sW1: [32][64]    @ 12288  (2048)  W1 chunk
//  sW2: [64][64]    @ 14336  (4096)  W2 (resident whole tile)
//  sO : [128][64]   @ 8192   (8192)  epilogue buffer, aliases sA+sW1+half sW2
#define OFF_H  0
#define OFF_A  8192
#define OFF_W1 12288
#define OFF_W2 14336
#define OFF_O  8192
#define SMEM_FLOATS 18432   // 73728 bytes

typedef unsigned long long u64t;

__device__ __forceinline__ u64t bcast2(float x) {
    u64t r;
    asm("mov.b64 %0, {%1, %1};" : "=l"(r) : "f"(x));
    return r;
}
__device__ __forceinline__ void unpack2(u64t v, float &x, float &y) {
    asm("mov.b64 {%0, %1}, %2;" : "=f"(x), "=f"(y) : "l"(v));
}
__device__ __forceinline__ void ffma2(u64t &d, u64t a, u64t b) {
    asm("fma.rn.f32x2 %0, %1, %2, %0;" : "+l"(d) : "l"(a), "l"(b));
}
__device__ __forceinline__ float silu_f(float x) {
    return x / (1.0f + __expf(-x));
}

extern "C" __global__ void __launch_bounds__(THREADS, 3)
edge_update_kernel(const float* __restrict__ node,
                   const float* __restrict__ ef,
                   const int*   __restrict__ src,
                   const int*   __restrict__ dst,
                   const float* __restrict__ W1,
                   const float* __restrict__ b1,
                   const float* __restrict__ W2,
                   const float* __restrict__ b2,
                   const float* __restrict__ gamma,
                   const float* __restrict__ beta,
                   float*       __restrict__ out,
                   int E)
{
    extern __shared__ float sm[];
    float* sH  = sm + OFF_H;
    float* sA  = sm + OFF_A;
    float* sW1 = sm + OFF_W1;
    float* sW2 = sm + OFF_W2;
    float* sO  = sm + OFF_O;

    const int tid  = threadIdx.x;
    const int tc   = tid & 7;    // channel group 0..7 (8 channels each)
    const int te   = tid >> 3;   // edge group    0..15 (8 edges each)
    const int base = blockIdx.x * TILE_E;

    // per-thread owned edge for staging
    const int eg  = base + tid;
    const int egc = (eg < E) ? eg : (E - 1);
    const float* srcRow = node + (size_t)src[egc] * D;
    const float* dstRow = node + (size_t)dst[egc] * D;
    const float* efRow  = ef   + (size_t)egc * D;

    // stage W2 once (4096 floats = 1024 float4)
    {
        const float4* g = (const float4*)W2;
        float4* s = (float4*)sW2;
        #pragma unroll
        for (int r = 0; r < 8; ++r) s[r * 128 + tid] = g[r * 128 + tid];
    }

    // ---------------- layer 1: [128,192] x [192,64] ----------------
    u64t acc[8][4];
    #pragma unroll
    for (int i = 0; i < 8; ++i)
        #pragma unroll
        for (int j = 0; j < 4; ++j) acc[i][j] = 0ULL;

    #pragma unroll 1
    for (int ch = 0; ch < 6; ++ch) {
        __syncthreads();
        // stage A chunk (32 k-values of this thread's edge), transposed
        const float* p = (ch < 2) ? srcRow : (ch < 4 ? dstRow : efRow);
        const float4* g = (const float4*)(p + (ch & 1) * 32);
        #pragma unroll
        for (int i = 0; i < 8; ++i) {
            float4 v = g[i];
            sA[(i * 4 + 0) * TILE_E + tid] = v.x;
            sA[(i * 4 + 1) * TILE_E + tid] = v.y;
            sA[(i * 4 + 2) * TILE_E + tid] = v.z;
            sA[(i * 4 + 3) * TILE_E + tid] = v.w;
        }
        // stage W1 chunk rows [ch*32, ch*32+32)
        {
            const float4* gw = (const float4*)(W1 + ch * 32 * D);
            float4* sw = (float4*)sW1;
            #pragma unroll
            for (int r = 0; r < 4; ++r) sw[r * 128 + tid] = gw[r * 128 + tid];
        }
        __syncthreads();

        #pragma unroll 4
        for (int kk = 0; kk < BK; ++kk) {
            float4 a0 = *(const float4*)&sA[kk * TILE_E + te * 8];
            float4 a1 = *(const float4*)&sA[kk * TILE_E + te * 8 + 4];
            ulonglong2 bb0 = *(const ulonglong2*)&sW1[kk * D + tc * 8];
            ulonglong2 bb1 = *(const ulonglong2*)&sW1[kk * D + tc * 8 + 4];
            u64t b[4] = { bb0.x, bb0.y, bb1.x, bb1.y };
            u64t a2[8];
            a2[0] = bcast2(a0.x); a2[1] = bcast2(a0.y);
            a2[2] = bcast2(a0.z); a2[3] = bcast2(a0.w);
            a2[4] = bcast2(a1.x); a2[5] = bcast2(a1.y);
            a2[6] = bcast2(a1.z); a2[7] = bcast2(a1.w);
            #pragma unroll
            for (int i = 0; i < 8; ++i) {
                ffma2(acc[i][0], a2[i], b[0]);
                ffma2(acc[i][1], a2[i], b[1]);
                ffma2(acc[i][2], a2[i], b[2]);
                ffma2(acc[i][3], a2[i], b[3]);
            }
        }
    }

    // bias + SiLU, write h1 transposed into sH[c][e]
    {
        float hv[8][8];
        #pragma unroll
        for (int i = 0; i < 8; ++i)
            #pragma unroll
            for (int jp = 0; jp < 4; ++jp)
                unpack2(acc[i][jp], hv[i][2 * jp], hv[i][2 * jp + 1]);
        #pragma unroll
        for (int j = 0; j < 8; ++j) {
            float bias = b1[tc * 8 + j];
            float v[8];
            #pragma unroll
            for (int i = 0; i < 8; ++i) v[i] = silu_f(hv[i][j] + bias);
            *(float4*)&sH[(tc * 8 + j) * TILE_E + te * 8]     = make_float4(v[0], v[1], v[2], v[3]);
            *(float4*)&sH[(tc * 8 + j) * TILE_E + te * 8 + 4] = make_float4(v[4], v[5], v[6], v[7]);
        }
    }
    __syncthreads();

    // ---------------- layer 2: [128,64] x [64,64] ----------------
    #pragma unroll
    for (int i = 0; i < 8; ++i)
        #pragma unroll
        for (int j = 0; j < 4; ++j) acc[i][j] = 0ULL;

    #pragma unroll 4
    for (int kk = 0; kk < 64; ++kk) {
        float4 a0 = *(const float4*)&sH[kk * TILE_E + te * 8];
        float4 a1 = *(const float4*)&sH[kk * TILE_E + te * 8 + 4];
        ulonglong2 bb0 = *(const ulonglong2*)&sW2[kk * D + tc * 8];
        ulonglong2 bb1 = *(const ulonglong2*)&sW2[kk * D + tc * 8 + 4];
        u64t b[4] = { bb0.x, bb0.y, bb1.x, bb1.y };
        u64t a2[8];
        a2[0] = bcast2(a0.x); a2[1] = bcast2(a0.y);
        a2[2] = bcast2(a0.z); a2[3] = bcast2(a0.w);
        a2[4] = bcast2(a1.x); a2[5] = bcast2(a1.y);
        a2[6] = bcast2(a1.z); a2[7] = bcast2(a1.w);
        #pragma unroll
        for (int i = 0; i < 8; ++i) {
            ffma2(acc[i][0], a2[i], b[0]);
            ffma2(acc[i][1], a2[i], b[1]);
            ffma2(acc[i][2], a2[i], b[2]);
            ffma2(acc[i][3], a2[i], b[3]);
        }
    }
    __syncthreads();   // everyone done with sA/sW1/sW2/sH reads before sO overwrite

    // ---------------- epilogue: residual, stage rows into sO ----------------
    {
        float h2[8][8];
        #pragma unroll
        for (int i = 0; i < 8; ++i)
            #pragma unroll
            for (int jp = 0; jp < 4; ++jp)
                unpack2(acc[i][jp], h2[i][2 * jp], h2[i][2 * jp + 1]);
        float bias2[8];
        #pragma unroll
        for (int j = 0; j < 8; ++j) bias2[j] = b2[tc * 8 + j];

        #pragma unroll
        for (int i = 0; i < 8; ++i) {
            int le = te * 8 + i;
            int ge = base + le;
            int gec = (ge < E) ? ge : (E - 1);
            const float4* efr = (const float4*)(ef + (size_t)gec * D + tc * 8);
            float4 f0 = efr[0];
            float4 f1 = efr[1];
            float o0 = f0.x + silu_f(h2[i][0] + bias2[0]);
            float o1 = f0.y + silu_f(h2[i][1] + bias2[1]);
            float o2 = f0.z + silu_f(h2[i][2] + bias2[2]);
            float o3 = f0.w + silu_f(h2[i][3] + bias2[3]);
            float o4 = f1.x + silu_f(h2[i][4] + bias2[4]);
            float o5 = f1.y + silu_f(h2[i][5] + bias2[5]);
            float o6 = f1.z + silu_f(h2[i][6] + bias2[6]);
            float o7 = f1.w + silu_f(h2[i][7] + bias2[7]);
            *(float4*)&sO[le * D + tc * 8]     = make_float4(o0, o1, o2, o3);
            *(float4*)&sO[le * D + tc * 8 + 4] = make_float4(o4, o5, o6, o7);
        }
    }
    __syncthreads();

    // ---------------- LayerNorm + store (warp per 32 edges, lane = channel) ----
    {
        const int warp = tid >> 5;
        const int lane = tid & 31;
        const float g0  = gamma[lane];
        const float g1  = gamma[lane + 32];
        const float be0 = beta[lane];
        const float be1 = beta[lane + 32];
        const float inv64 = 1.0f / 64.0f;
        for (int e = warp * 32; e < warp * 32 + 32; ++e) {
            float x0 = sO[e * D + lane];
            float x1 = sO[e * D + lane + 32];
            float s  = x0 + x1;
            float sq = x0 * x0 + x1 * x1;
            #pragma unroll
            for (int o = 16; o > 0; o >>= 1) {
                s  += __shfl_xor_sync(0xffffffffu, s,  o);
                sq += __shfl_xor_sync(0xffffffffu, sq, o);
            }
            float mu  = s * inv64;
            float var = sq * inv64 - mu * mu;
            float rs  = rsqrtf(var + 1e-5f);
            int ge = base + e;
            if (ge < E) {
                out[(size_t)ge * D + lane]      = (x0 - mu) * rs * g0 + be0;
                out[(size_t)ge * D + lane + 32] = (x1 - mu) * rs * g1 + be1;
            }
        }
    }
}

extern "C" void kernel_launch(void* const* d_in, const int* in_sizes, int n_in,
                              void* d_out, int out_size)
{
    const float* node  = (const float*)d_in[0];
    const float* ef    = (const float*)d_in[1];
    const int*   src   = (const int*)d_in[2];
    const int*   dst   = (const int*)d_in[3];
    const float* W1    = (const float*)d_in[4];
    const float* b1    = (const float*)d_in[5];
    const float* W2    = (const float*)d_in[6];
    const float* b2    = (const float*)d_in[7];
    const float* gamma = (const float*)d_in[8];
    const float* beta  = (const float*)d_in[9];
    float* out = (float*)d_out;

    const int E = in_sizes[2];           // number of edges (src_idxs count)
    const int nTiles = (E + TILE_E - 1) / TILE_E;

    cudaFuncSetAttribute(edge_update_kernel,
                         cudaFuncAttributeMaxDynamicSharedMemorySize,
                         SMEM_FLOATS * sizeof(float));
    edge_update_kernel<<<nTiles, THREADS, SMEM_FLOATS * sizeof(float)>>>(
        node, ef, src, dst, W1, b1, W2, b2, gamma, beta, out, E);
}

// round 3
// speedup vs baseline: 2.7154x; 2.7154x over previous
#include <cuda_runtime.h>
#include <cuda_bf16.h>
#include <cstdint>

#define THREADS 128
#define TILE_E  128
#define AK 72            // padded row stride (bf16 elems) for A/h tiles
#define WK 72            // padded row stride for weight tiles

// ---------------- shared memory byte offsets ----------------
#define SM_B1 0
#define SM_B2 256
#define SM_G  512
#define SM_BT 768
#define SM_AH 1024
#define SM_AL (SM_AH + 128*AK*2)      // 19456
#define SM_WH (SM_AL + 128*AK*2)      // 37888
#define SM_WL (SM_WH + 64*WK*2)       // 47104
#define SMEM_BYTES (SM_WL + 64*WK*2)  // 56320

// bf16-split weights, natural [k][n] layout
static __device__ __nv_bfloat16 g_W1h[192 * 64];
static __device__ __nv_bfloat16 g_W1l[192 * 64];
static __device__ __nv_bfloat16 g_W2h[64 * 64];
static __device__ __nv_bfloat16 g_W2l[64 * 64];

// ---------------- ptx helpers ----------------
__device__ __forceinline__ uint32_t smem_u32(const void* p) {
    uint32_t a;
    asm("{ .reg .u64 t; cvta.to.shared.u64 t, %1; cvt.u32.u64 %0, t; }" : "=r"(a) : "l"(p));
    return a;
}
__device__ __forceinline__ void ldsm_x4(uint32_t& r0, uint32_t& r1, uint32_t& r2, uint32_t& r3,
                                        uint32_t addr) {
    asm volatile("ldmatrix.sync.aligned.m8n8.x4.shared.b16 {%0,%1,%2,%3}, [%4];"
                 : "=r"(r0), "=r"(r1), "=r"(r2), "=r"(r3) : "r"(addr));
}
__device__ __forceinline__ void ldsm_x4_t(uint32_t& r0, uint32_t& r1, uint32_t& r2, uint32_t& r3,
                                          uint32_t addr) {
    asm volatile("ldmatrix.sync.aligned.m8n8.x4.trans.shared.b16 {%0,%1,%2,%3}, [%4];"
                 : "=r"(r0), "=r"(r1), "=r"(r2), "=r"(r3) : "r"(addr));
}
__device__ __forceinline__ void mma_bf16(float* c, const uint32_t* a, const uint32_t* b) {
    asm volatile(
        "mma.sync.aligned.m16n8k16.row.col.f32.bf16.bf16.f32 "
        "{%0,%1,%2,%3}, {%4,%5,%6,%7}, {%8,%9}, {%0,%1,%2,%3};"
        : "+f"(c[0]), "+f"(c[1]), "+f"(c[2]), "+f"(c[3])
        : "r"(a[0]), "r"(a[1]), "r"(a[2]), "r"(a[3]), "r"(b[0]), "r"(b[1]));
}

// ---------------- math helpers ----------------
__device__ __forceinline__ float silu_f(float x) { return x / (1.0f + __expf(-x)); }

__device__ __forceinline__ void split_pair(float a, float b, uint32_t& hi, uint32_t& lo) {
    __nv_bfloat162 h = __floats2bfloat162_rn(a, b);
    float la = a - __low2float(h);
    float lb = b - __high2float(h);
    __nv_bfloat162 l = __floats2bfloat162_rn(la, lb);
    hi = *(uint32_t*)&h;
    lo = *(uint32_t*)&l;
}

// stage one gathered fp32 row (64 floats) into hi/lo bf16 tiles, padded stride
__device__ __forceinline__ void stage_A_row(unsigned char* sm, int row,
                                            const float* __restrict__ p) {
    unsigned char* dh = sm + SM_AH + row * (AK * 2);
    unsigned char* dl = sm + SM_AL + row * (AK * 2);
    #pragma unroll
    for (int i = 0; i < 8; ++i) {
        float4 x = ((const float4*)p)[2 * i];
        float4 y = ((const float4*)p)[2 * i + 1];
        uint32_t h0, h1, h2, h3, l0, l1, l2, l3;
        split_pair(x.x, x.y, h0, l0);
        split_pair(x.z, x.w, h1, l1);
        split_pair(y.x, y.y, h2, l2);
        split_pair(y.z, y.w, h3, l3);
        *(uint4*)(dh + i * 16) = make_uint4(h0, h1, h2, h3);
        *(uint4*)(dl + i * 16) = make_uint4(l0, l1, l2, l3);
    }
}

// stage a 64x64 weight chunk (hi+lo) from global scratch, padded stride
__device__ __forceinline__ void stage_W(unsigned char* sm,
                                        const __nv_bfloat16* gh, const __nv_bfloat16* gl,
                                        int tid) {
    int row = tid >> 1, half = tid & 1;
    const uint4* sh = (const uint4*)(gh + row * 64 + half * 32);
    const uint4* sl = (const uint4*)(gl + row * 64 + half * 32);
    uint4* dh = (uint4*)(sm + SM_WH + row * (WK * 2) + half * 64);
    uint4* dl = (uint4*)(sm + SM_WL + row * (WK * 2) + half * 64);
    #pragma unroll
    for (int i = 0; i < 4; ++i) { dh[i] = sh[i]; dl[i] = sl[i]; }
}

// one K=64 chunk, bf16x3 split (hi*hi + lo*hi + hi*lo), accumulate into acc
__device__ __forceinline__ void gemm_chunk(uint32_t aH, uint32_t aL,
                                           uint32_t wH, uint32_t wL,
                                           int m0, int lane, float acc[2][8][4]) {
    const uint32_t arow = (uint32_t)(lane & 15);
    const uint32_t acol = (uint32_t)((lane >> 4) * 8);
    #pragma unroll 1
    for (int p = 0; p < 3; ++p) {
        uint32_t ab = (p == 1) ? aL : aH;
        uint32_t wb = (p == 2) ? wL : wH;
        #pragma unroll
        for (int k = 0; k < 4; ++k) {
            uint32_t a[2][4];
            #pragma unroll
            for (int mt = 0; mt < 2; ++mt) {
                uint32_t addr = ab + (((uint32_t)(m0 + mt * 16) + arow) * AK + k * 16 + acol) * 2;
                ldsm_x4(a[mt][0], a[mt][1], a[mt][2], a[mt][3], addr);
            }
            uint32_t b[4][4];
            #pragma unroll
            for (int nt = 0; nt < 4; ++nt) {
                uint32_t addr = wb + (((uint32_t)(k * 16) + arow) * WK + nt * 16 + acol) * 2;
                ldsm_x4_t(b[nt][0], b[nt][1], b[nt][2], b[nt][3], addr);
            }
            #pragma unroll
            for (int mt = 0; mt < 2; ++mt)
                #pragma unroll
                for (int nt = 0; nt < 8; ++nt)
                    mma_bf16(acc[mt][nt], a[mt], &b[nt >> 1][(nt & 1) * 2]);
        }
    }
}

// ---------------- weight prep: bf16 split ----------------
__global__ void prep_weights(const float* __restrict__ W1, const float* __restrict__ W2) {
    int i = blockIdx.x * blockDim.x + threadIdx.x;
    if (i < 192 * 64) {
        float x = W1[i];
        __nv_bfloat16 h = __float2bfloat16_rn(x);
        g_W1h[i] = h;
        g_W1l[i] = __float2bfloat16_rn(x - __bfloat162float(h));
    } else if (i < 192 * 64 + 64 * 64) {
        int j = i - 192 * 64;
        float x = W2[j];
        __nv_bfloat16 h = __float2bfloat16_rn(x);
        g_W2h[j] = h;
        g_W2l[j] = __float2bfloat16_rn(x - __bfloat162float(h));
    }
}

// ---------------- main fused kernel ----------------
extern "C" __global__ void __launch_bounds__(THREADS, 3)
edge_update_hmma(const float* __restrict__ node,
                 const float* __restrict__ ef,
                 const int*   __restrict__ src,
                 const int*   __restrict__ dst,
                 const float* __restrict__ b1,
                 const float* __restrict__ b2,
                 const float* __restrict__ gamma,
                 const float* __restrict__ beta,
                 float*       __restrict__ out,
                 int E)
{
    extern __shared__ __align__(128) unsigned char sm[];
    const uint32_t smem_base = smem_u32(sm);
    const int tid  = threadIdx.x;
    const int lane = tid & 31;
    const int m0   = (tid >> 5) * 32;     // warp's edge-row base within tile
    const int base = blockIdx.x * TILE_E;

    if (tid < 64) {
        ((float*)(sm + SM_B1))[tid] = b1[tid];
        ((float*)(sm + SM_B2))[tid] = b2[tid];
        ((float*)(sm + SM_G))[tid]  = gamma[tid];
        ((float*)(sm + SM_BT))[tid] = beta[tid];
    }

    const int eg = base + tid;
    const int ec = (eg < E) ? eg : (E - 1);
    const float* srcRow = node + (size_t)src[ec] * 64;
    const float* dstRow = node + (size_t)dst[ec] * 64;
    const float* efRow  = ef   + (size_t)ec * 64;

    float acc[2][8][4];
    #pragma unroll
    for (int mt = 0; mt < 2; ++mt)
        #pragma unroll
        for (int nt = 0; nt < 8; ++nt)
            #pragma unroll
            for (int j = 0; j < 4; ++j) acc[mt][nt][j] = 0.f;

    // ---------------- layer 1: 3 K-chunks of 64 ----------------
    #pragma unroll 1
    for (int c = 0; c < 3; ++c) {
        __syncthreads();   // prior chunk's ldmatrix reads complete before restage
        const float* p = (c == 0) ? srcRow : (c == 1) ? dstRow : efRow;
        stage_A_row(sm, tid, p);
        stage_W(sm, g_W1h + c * 4096, g_W1l + c * 4096, tid);
        __syncthreads();
        gemm_chunk(smem_base + SM_AH, smem_base + SM_AL,
                   smem_base + SM_WH, smem_base + SM_WL, m0, lane, acc);
    }

    // ---------------- epilogue 1: bias + SiLU, restage h as bf16 hi/lo ----------------
    __syncthreads();            // everyone done reading W1 chunk & own A rows
    stage_W(sm, g_W2h, g_W2l, tid);
    {
        const float* b1s = (const float*)(sm + SM_B1);
        #pragma unroll
        for (int mt = 0; mt < 2; ++mt)
            #pragma unroll
            for (int nt = 0; nt < 8; ++nt) {
                int col = nt * 8 + (lane & 3) * 2;
                float bb0 = b1s[col], bb1 = b1s[col + 1];
                int r0 = m0 + mt * 16 + (lane >> 2);
                int r1 = r0 + 8;
                float h00 = silu_f(acc[mt][nt][0] + bb0);
                float h01 = silu_f(acc[mt][nt][1] + bb1);
                float h10 = silu_f(acc[mt][nt][2] + bb0);
                float h11 = silu_f(acc[mt][nt][3] + bb1);
                uint32_t hi, lo;
                split_pair(h00, h01, hi, lo);
                *(uint32_t*)(sm + SM_AH + r0 * (AK * 2) + col * 2) = hi;
                *(uint32_t*)(sm + SM_AL + r0 * (AK * 2) + col * 2) = lo;
                split_pair(h10, h11, hi, lo);
                *(uint32_t*)(sm + SM_AH + r1 * (AK * 2) + col * 2) = hi;
                *(uint32_t*)(sm + SM_AL + r1 * (AK * 2) + col * 2) = lo;
            }
    }
    #pragma unroll
    for (int mt = 0; mt < 2; ++mt)
        #pragma unroll
        for (int nt = 0; nt < 8; ++nt)
            #pragma unroll
            for (int j = 0; j < 4; ++j) acc[mt][nt][j] = 0.f;
    __syncthreads();

    // ---------------- layer 2: K=64 ----------------
    gemm_chunk(smem_base + SM_AH, smem_base + SM_AL,
               smem_base + SM_WH, smem_base + SM_WL, m0, lane, acc);

    // ---------------- epilogue 2: residual + LayerNorm on fragments ----------------
    {
        const float* b2s = (const float*)(sm + SM_B2);
        const float* gs  = (const float*)(sm + SM_G);
        const float* bts = (const float*)(sm + SM_BT);
        #pragma unroll
        for (int mt = 0; mt < 2; ++mt) {
            #pragma unroll
            for (int half = 0; half < 2; ++half) {
                int r = m0 + mt * 16 + (lane >> 2) + half * 8;
                int e = base + r;
                int eclamp = (e < E) ? e : (E - 1);
                const float* efr = ef + (size_t)eclamp * 64;
                float o[16];
                float s = 0.f, sq = 0.f;
                #pragma unroll
                for (int nt = 0; nt < 8; ++nt) {
                    int col = nt * 8 + (lane & 3) * 2;
                    float2 f = *(const float2*)(efr + col);
                    float v0 = f.x + silu_f(acc[mt][nt][half * 2 + 0] + b2s[col]);
                    float v1 = f.y + silu_f(acc[mt][nt][half * 2 + 1] + b2s[col + 1]);
                    o[nt * 2] = v0;
                    o[nt * 2 + 1] = v1;
                    s += v0 + v1;
                    sq += v0 * v0 + v1 * v1;
                }
                s  += __shfl_xor_sync(0xffffffffu, s, 1);
                sq += __shfl_xor_sync(0xffffffffu, sq, 1);
                s  += __shfl_xor_sync(0xffffffffu, s, 2);
                sq += __shfl_xor_sync(0xffffffffu, sq, 2);
                float mu  = s * (1.0f / 64.0f);
                float var = sq * (1.0f / 64.0f) - mu * mu;
                float rs  = rsqrtf(var + 1e-5f);
                if (e < E) {
                    float* op = out + (size_t)e * 64;
                    #pragma unroll
                    for (int nt = 0; nt < 8; ++nt) {
                        int col = nt * 8 + (lane & 3) * 2;
                        float2 w;
                        w.x = (o[nt * 2]     - mu) * rs * gs[col]     + bts[col];
                        w.y = (o[nt * 2 + 1] - mu) * rs * gs[col + 1] + bts[col + 1];
                        *(float2*)(op + col) = w;
                    }
                }
            }
        }
    }
}

extern "C" void kernel_launch(void* const* d_in, const int* in_sizes, int n_in,
                              void* d_out, int out_size)
{
    const float* node  = (const float*)d_in[0];
    const float* ef    = (const float*)d_in[1];
    const int*   src   = (const int*)d_in[2];
    const int*   dst   = (const int*)d_in[3];
    const float* W1    = (const float*)d_in[4];
    const float* b1    = (const float*)d_in[5];
    const float* W2    = (const float*)d_in[6];
    const float* b2    = (const float*)d_in[7];
    const float* gamma = (const float*)d_in[8];
    const float* beta  = (const float*)d_in[9];
    float* out = (float*)d_out;

    const int E = in_sizes[2];
    const int nTiles = (E + TILE_E - 1) / TILE_E;

    prep_weights<<<64, 256>>>(W1, W2);

    cudaFuncSetAttribute(edge_update_hmma,
                         cudaFuncAttributeMaxDynamicSharedMemorySize, SMEM_BYTES);
    edge_update_hmma<<<nTiles, THREADS, SMEM_BYTES>>>(
        node, ef, src, dst, b1, b2, gamma, beta, out, E);
}

// round 6
// speedup vs baseline: 2.7936x; 1.0288x over previous
#include <cuda_runtime.h>
#include <cuda_bf16.h>
#include <cstdint>

#define THREADS 128
#define TILE_E  128
#define AK 72            // padded row stride (bf16 elems) for A/h tiles
#define WK 72            // padded row stride for weight tiles

// ---------------- shared memory byte offsets ----------------
#define SM_B1 0
#define SM_B2 256
#define SM_G  512
#define SM_BT 768
#define SM_AH 1024
#define SM_AL (SM_AH + 128*AK*2)      // 19456
#define SM_WH (SM_AL + 128*AK*2)      // 37888
#define SM_WL (SM_WH + 64*WK*2)       // 47104
#define SMEM_BYTES (SM_WL + 64*WK*2)  // 56320

// bf16-split weights, natural [k][n] layout
static __device__ __nv_bfloat16 g_W1h[192 * 64];
static __device__ __nv_bfloat16 g_W1l[192 * 64];
static __device__ __nv_bfloat16 g_W2h[64 * 64];
static __device__ __nv_bfloat16 g_W2l[64 * 64];

// ---------------- ptx helpers ----------------
__device__ __forceinline__ uint32_t smem_u32(const void* p) {
    uint32_t a;
    asm("{ .reg .u64 t; cvta.to.shared.u64 t, %1; cvt.u32.u64 %0, t; }" : "=r"(a) : "l"(p));
    return a;
}
__device__ __forceinline__ void ldsm_x4(uint32_t* r, uint32_t addr) {
    asm volatile("ldmatrix.sync.aligned.m8n8.x4.shared.b16 {%0,%1,%2,%3}, [%4];"
                 : "=r"(r[0]), "=r"(r[1]), "=r"(r[2]), "=r"(r[3]) : "r"(addr));
}
__device__ __forceinline__ void ldsm_x4_t(uint32_t* r, uint32_t addr) {
    asm volatile("ldmatrix.sync.aligned.m8n8.x4.trans.shared.b16 {%0,%1,%2,%3}, [%4];"
                 : "=r"(r[0]), "=r"(r[1]), "=r"(r[2]), "=r"(r[3]) : "r"(addr));
}
__device__ __forceinline__ void mma_bf16(float* c, const uint32_t* a, const uint32_t* b) {
    asm volatile(
        "mma.sync.aligned.m16n8k16.row.col.f32.bf16.bf16.f32 "
        "{%0,%1,%2,%3}, {%4,%5,%6,%7}, {%8,%9}, {%0,%1,%2,%3};"
        : "+f"(c[0]), "+f"(c[1]), "+f"(c[2]), "+f"(c[3])
        : "r"(a[0]), "r"(a[1]), "r"(a[2]), "r"(a[3]), "r"(b[0]), "r"(b[1]));
}
__device__ __forceinline__ void prefetch_l2(const void* p) {
    asm volatile("prefetch.global.L2 [%0];" :: "l"(p));
}

// ---------------- math helpers ----------------
__device__ __forceinline__ float silu_f(float x) { return x / (1.0f + __expf(-x)); }

__device__ __forceinline__ void split_pair(float a, float b, uint32_t& hi, uint32_t& lo) {
    __nv_bfloat162 h = __floats2bfloat162_rn(a, b);
    float la = a - __low2float(h);
    float lb = b - __high2float(h);
    __nv_bfloat162 l = __floats2bfloat162_rn(la, lb);
    hi = *(uint32_t*)&h;
    lo = *(uint32_t*)&l;
}

// stage one gathered fp32 row (64 floats) into hi/lo bf16 tiles, padded stride
__device__ __forceinline__ void stage_A_row(unsigned char* sm, int row,
                                            const float* __restrict__ p) {
    unsigned char* dh = sm + SM_AH + row * (AK * 2);
    unsigned char* dl = sm + SM_AL + row * (AK * 2);
    #pragma unroll
    for (int i = 0; i < 8; ++i) {
        float4 x = ((const float4*)p)[2 * i];
        float4 y = ((const float4*)p)[2 * i + 1];
        uint32_t h0, h1, h2, h3, l0, l1, l2, l3;
        split_pair(x.x, x.y, h0, l0);
        split_pair(x.z, x.w, h1, l1);
        split_pair(y.x, y.y, h2, l2);
        split_pair(y.z, y.w, h3, l3);
        *(uint4*)(dh + i * 16) = make_uint4(h0, h1, h2, h3);
        *(uint4*)(dl + i * 16) = make_uint4(l0, l1, l2, l3);
    }
}

// stage a 64x64 weight chunk (hi+lo) from global scratch, padded stride
__device__ __forceinline__ void stage_W(unsigned char* sm,
                                        const __nv_bfloat16* gh, const __nv_bfloat16* gl,
                                        int tid) {
    int row = tid >> 1, half = tid & 1;
    const uint4* sh = (const uint4*)(gh + row * 64 + half * 32);
    const uint4* sl = (const uint4*)(gl + row * 64 + half * 32);
    uint4* dh = (uint4*)(sm + SM_WH + row * (WK * 2) + half * 64);
    uint4* dl = (uint4*)(sm + SM_WL + row * (WK * 2) + half * 64);
    #pragma unroll
    for (int i = 0; i < 4; ++i) { dh[i] = sh[i]; dl[i] = sl[i]; }
}

// one K=64 chunk, bf16x3 split, per-k fragment caching.
// product order lo*hi -> hi*hi -> hi*lo keeps peak live fragments at 32 regs.
__device__ __forceinline__ void gemm_chunk(uint32_t aH, uint32_t aL,
                                           uint32_t wH, uint32_t wL,
                                           int m0, int lane, float acc[2][8][4]) {
    const uint32_t arow = (uint32_t)(lane & 15);
    const uint32_t acol = (uint32_t)((lane >> 4) * 8);
    #pragma unroll
    for (int k = 0; k < 4; ++k) {
        const uint32_t aoff = (arow * AK + k * 16 + acol) * 2;
        const uint32_t woff = (((uint32_t)(k * 16) + arow) * WK + acol) * 2;

        uint32_t a_lo[2][4], b_hi[4][4];
        #pragma unroll
        for (int mt = 0; mt < 2; ++mt)
            ldsm_x4(a_lo[mt], aL + aoff + (uint32_t)(m0 + mt * 16) * (AK * 2));
        #pragma unroll
        for (int nt = 0; nt < 4; ++nt)
            ldsm_x4_t(b_hi[nt], wH + woff + (uint32_t)(nt * 16) * 2);
        #pragma unroll
        for (int mt = 0; mt < 2; ++mt)
            #pragma unroll
            for (int nt = 0; nt < 8; ++nt)
                mma_bf16(acc[mt][nt], a_lo[mt], &b_hi[nt >> 1][(nt & 1) * 2]);

        uint32_t a_hi[2][4];
        #pragma unroll
        for (int mt = 0; mt < 2; ++mt)
            ldsm_x4(a_hi[mt], aH + aoff + (uint32_t)(m0 + mt * 16) * (AK * 2));
        #pragma unroll
        for (int mt = 0; mt < 2; ++mt)
            #pragma unroll
            for (int nt = 0; nt < 8; ++nt)
                mma_bf16(acc[mt][nt], a_hi[mt], &b_hi[nt >> 1][(nt & 1) * 2]);

        uint32_t b_lo[4][4];
        #pragma unroll
        for (int nt = 0; nt < 4; ++nt)
            ldsm_x4_t(b_lo[nt], wL + woff + (uint32_t)(nt * 16) * 2);
        #pragma unroll
        for (int mt = 0; mt < 2; ++mt)
            #pragma unroll
            for (int nt = 0; nt < 8; ++nt)
                mma_bf16(acc[mt][nt], a_hi[mt], &b_lo[nt >> 1][(nt & 1) * 2]);
    }
}

// ---------------- weight prep: bf16 split ----------------
__global__ void prep_weights(const float* __restrict__ W1, const float* __restrict__ W2) {
    int i = blockIdx.x * blockDim.x + threadIdx.x;
    if (i < 192 * 64) {
        float x = W1[i];
        __nv_bfloat16 h = __float2bfloat16_rn(x);
        g_W1h[i] = h;
        g_W1l[i] = __float2bfloat16_rn(x - __bfloat162float(h));
    } else if (i < 192 * 64 + 64 * 64) {
        int j = i - 192 * 64;
        float x = W2[j];
        __nv_bfloat16 h = __float2bfloat16_rn(x);
        g_W2h[j] = h;
        g_W2l[j] = __float2bfloat16_rn(x - __bfloat162float(h));
    }
}

// ---------------- main fused kernel ----------------
extern "C" __global__ void __launch_bounds__(THREADS, 3)
edge_update_hmma(const float* __restrict__ node,
                 const float* __restrict__ ef,
                 const int*   __restrict__ src,
                 const int*   __restrict__ dst,
                 const float* __restrict__ b1,
                 const float* __restrict__ b2,
                 const float* __restrict__ gamma,
                 const float* __restrict__ beta,
                 float*       __restrict__ out,
                 int E)
{
    extern __shared__ __align__(128) unsigned char sm[];
    const uint32_t smem_base = smem_u32(sm);
    const int tid  = threadIdx.x;
    const int lane = tid & 31;
    const int m0   = (tid >> 5) * 32;     // warp's edge-row base within tile
    const int base = blockIdx.x * TILE_E;

    if (tid < 64) {
        ((float*)(sm + SM_B1))[tid] = b1[tid];
        ((float*)(sm + SM_B2))[tid] = b2[tid];
        ((float*)(sm + SM_G))[tid]  = gamma[tid];
        ((float*)(sm + SM_BT))[tid] = beta[tid];
    }

    const int eg = base + tid;
    const int ec = (eg < E) ? eg : (E - 1);
    const float* srcRow = node + (size_t)src[ec] * 64;
    const float* dstRow = node + (size_t)dst[ec] * 64;
    const float* efRow  = ef   + (size_t)ec * 64;

    // warm L2 for the later chunks' gathers while chunk 0 runs
    prefetch_l2(dstRow);
    prefetch_l2(dstRow + 32);
    prefetch_l2(efRow);
    prefetch_l2(efRow + 32);

    float acc[2][8][4];
    #pragma unroll
    for (int mt = 0; mt < 2; ++mt)
        #pragma unroll
        for (int nt = 0; nt < 8; ++nt)
            #pragma unroll
            for (int j = 0; j < 4; ++j) acc[mt][nt][j] = 0.f;

    // ---------------- layer 1: 3 K-chunks of 64 ----------------
    #pragma unroll 1
    for (int c = 0; c < 3; ++c) {
        __syncthreads();   // prior chunk's ldmatrix reads complete before restage
        const float* p = (c == 0) ? srcRow : (c == 1) ? dstRow : efRow;
        stage_A_row(sm, tid, p);
        stage_W(sm, g_W1h + c * 4096, g_W1l + c * 4096, tid);
        __syncthreads();
        gemm_chunk(smem_base + SM_AH, smem_base + SM_AL,
                   smem_base + SM_WH, smem_base + SM_WL, m0, lane, acc);
    }

    // ---------------- epilogue 1: bias + SiLU, restage h as bf16 hi/lo ----------------
    __syncthreads();            // everyone done reading W1 chunk & own A rows
    stage_W(sm, g_W2h, g_W2l, tid);
    {
        const float* b1s = (const float*)(sm + SM_B1);
        #pragma unroll
        for (int mt = 0; mt < 2; ++mt)
            #pragma unroll
            for (int nt = 0; nt < 8; ++nt) {
                int col = nt * 8 + (lane & 3) * 2;
                float bb0 = b1s[col], bb1 = b1s[col + 1];
                int r0 = m0 + mt * 16 + (lane >> 2);
                int r1 = r0 + 8;
                float h00 = silu_f(acc[mt][nt][0] + bb0);
                float h01 = silu_f(acc[mt][nt][1] + bb1);
                float h10 = silu_f(acc[mt][nt][2] + bb0);
                float h11 = silu_f(acc[mt][nt][3] + bb1);
                uint32_t hi, lo;
                split_pair(h00, h01, hi, lo);
                *(uint32_t*)(sm + SM_AH + r0 * (AK * 2) + col * 2) = hi;
                *(uint32_t*)(sm + SM_AL + r0 * (AK * 2) + col * 2) = lo;
                split_pair(h10, h11, hi, lo);
                *(uint32_t*)(sm + SM_AH + r1 * (AK * 2) + col * 2) = hi;
                *(uint32_t*)(sm + SM_AL + r1 * (AK * 2) + col * 2) = lo;
            }
    }
    #pragma unroll
    for (int mt = 0; mt < 2; ++mt)
        #pragma unroll
        for (int nt = 0; nt < 8; ++nt)
            #pragma unroll
            for (int j = 0; j < 4; ++j) acc[mt][nt][j] = 0.f;
    __syncthreads();

    // ---------------- layer 2: K=64 ----------------
    gemm_chunk(smem_base + SM_AH, smem_base + SM_AL,
               smem_base + SM_WH, smem_base + SM_WL, m0, lane, acc);

    // ---------------- epilogue 2: residual + LayerNorm on fragments ----------------
    {
        const float* b2s = (const float*)(sm + SM_B2);
        const float* gs  = (const float*)(sm + SM_G);
        const float* bts = (const float*)(sm + SM_BT);
        #pragma unroll
        for (int mt = 0; mt < 2; ++mt) {
            #pragma unroll
            for (int half = 0; half < 2; ++half) {
                int r = m0 + mt * 16 + (lane >> 2) + half * 8;
                int e = base + r;
                int eclamp = (e < E) ? e : (E - 1);
                const float* efr = ef + (size_t)eclamp * 64;
                float o[16];
                float s = 0.f, sq = 0.f;
                #pragma unroll
                for (int nt = 0; nt < 8; ++nt) {
                    int col = nt * 8 + (lane & 3) * 2;
                    float2 f = *(const float2*)(efr + col);
                    float v0 = f.x + silu_f(acc[mt][nt][half * 2 + 0] + b2s[col]);
                    float v1 = f.y + silu_f(acc[mt][nt][half * 2 + 1] + b2s[col + 1]);
                    o[nt * 2] = v0;
                    o[nt * 2 + 1] = v1;
                    s += v0 + v1;
                    sq += v0 * v0 + v1 * v1;
                }
                s  += __shfl_xor_sync(0xffffffffu, s, 1);
                sq += __shfl_xor_sync(0xffffffffu, sq, 1);
                s  += __shfl_xor_sync(0xffffffffu, s, 2);
                sq += __shfl_xor_sync(0xffffffffu, sq, 2);
                float mu  = s * (1.0f / 64.0f);
                float var = sq * (1.0f / 64.0f) - mu * mu;
                float rs  = rsqrtf(var + 1e-5f);
                if (e < E) {
                    float* op = out + (size_t)e * 64;
                    #pragma unroll
                    for (int nt = 0; nt < 8; ++nt) {
                        int col = nt * 8 + (lane & 3) * 2;
                        float2 w;
                        w.x = (o[nt * 2]     - mu) * rs * gs[col]     + bts[col];
                        w.y = (o[nt * 2 + 1] - mu) * rs * gs[col + 1] + bts[col + 1];
                        *(float2*)(op + col) = w;
                    }
                }
            }
        }
    }
}

extern "C" void kernel_launch(void* const* d_in, const int* in_sizes, int n_in,
                              void* d_out, int out_size)
{
    const float* node  = (const float*)d_in[0];
    const float* ef    = (const float*)d_in[1];
    const int*   src   = (const int*)d_in[2];
    const int*   dst   = (const int*)d_in[3];
    const float* W1    = (const float*)d_in[4];
    const float* b1    = (const float*)d_in[5];
    const float* W2    = (const float*)d_in[6];
    const float* b2    = (const float*)d_in[7];
    const float* gamma = (const float*)d_in[8];
    const float* beta  = (const float*)d_in[9];
    float* out = (float*)d_out;

    const int E = in_sizes[2];
    const int nTiles = (E + TILE_E - 1) / TILE_E;

    prep_weights<<<64, 256>>>(W1, W2);

    cudaFuncSetAttribute(edge_update_hmma,
                         cudaFuncAttributeMaxDynamicSharedMemorySize, SMEM_BYTES);
    edge_update_hmma<<<nTiles, THREADS, SMEM_BYTES>>>(
        node, ef, src, dst, b1, b2, gamma, beta, out, E);
}

// round 7
// speedup vs baseline: 2.8953x; 1.0364x over previous
#include <cuda_runtime.h>
#include <cuda_bf16.h>
#include <cstdint>

#define THREADS 128
#define TILE_E  128
#define AK 72            // padded row stride (bf16 elems) for A/h tiles
#define WK 72            // padded row stride for weight tiles

// ---------------- shared memory byte offsets ----------------
#define SM_B1 0
#define SM_B2 256
#define SM_G  512
#define SM_BT 768
#define SM_AH 1024
#define SM_AL (SM_AH + 128*AK*2)      // 19456
#define SM_WH (SM_AL + 128*AK*2)      // 37888
#define SM_WL (SM_WH + 64*WK*2)       // 47104
#define SMEM_BYTES (SM_WL + 64*WK*2)  // 56320  (x4 CTAs = 225280 <= 227328)

// bf16-split weights, natural [k][n] layout
static __device__ __nv_bfloat16 g_W1h[192 * 64];
static __device__ __nv_bfloat16 g_W1l[192 * 64];
static __device__ __nv_bfloat16 g_W2h[64 * 64];
static __device__ __nv_bfloat16 g_W2l[64 * 64];

// ---------------- ptx helpers ----------------
__device__ __forceinline__ uint32_t smem_u32(const void* p) {
    uint32_t a;
    asm("{ .reg .u64 t; cvta.to.shared.u64 t, %1; cvt.u32.u64 %0, t; }" : "=r"(a) : "l"(p));
    return a;
}
__device__ __forceinline__ void ldsm_x4(uint32_t* r, uint32_t addr) {
    asm volatile("ldmatrix.sync.aligned.m8n8.x4.shared.b16 {%0,%1,%2,%3}, [%4];"
                 : "=r"(r[0]), "=r"(r[1]), "=r"(r[2]), "=r"(r[3]) : "r"(addr));
}
__device__ __forceinline__ void ldsm_x4_t(uint32_t* r, uint32_t addr) {
    asm volatile("ldmatrix.sync.aligned.m8n8.x4.trans.shared.b16 {%0,%1,%2,%3}, [%4];"
                 : "=r"(r[0]), "=r"(r[1]), "=r"(r[2]), "=r"(r[3]) : "r"(addr));
}
__device__ __forceinline__ void mma_bf16(float* c, const uint32_t* a, const uint32_t* b) {
    asm volatile(
        "mma.sync.aligned.m16n8k16.row.col.f32.bf16.bf16.f32 "
        "{%0,%1,%2,%3}, {%4,%5,%6,%7}, {%8,%9}, {%0,%1,%2,%3};"
        : "+f"(c[0]), "+f"(c[1]), "+f"(c[2]), "+f"(c[3])
        : "r"(a[0]), "r"(a[1]), "r"(a[2]), "r"(a[3]), "r"(b[0]), "r"(b[1]));
}
__device__ __forceinline__ void prefetch_l2(const void* p) {
    asm volatile("prefetch.global.L2 [%0];" :: "l"(p));
}

// ---------------- math helpers ----------------
__device__ __forceinline__ float silu_f(float x) { return x / (1.0f + __expf(-x)); }

__device__ __forceinline__ void split_pair(float a, float b, uint32_t& hi, uint32_t& lo) {
    __nv_bfloat162 h = __floats2bfloat162_rn(a, b);
    float la = a - __low2float(h);
    float lb = b - __high2float(h);
    __nv_bfloat162 l = __floats2bfloat162_rn(la, lb);
    hi = *(uint32_t*)&h;
    lo = *(uint32_t*)&l;
}

// stage one gathered fp32 row (64 floats) into hi/lo bf16 tiles, padded stride
__device__ __forceinline__ void stage_A_row(unsigned char* sm, int row,
                                            const float* __restrict__ p) {
    unsigned char* dh = sm + SM_AH + row * (AK * 2);
    unsigned char* dl = sm + SM_AL + row * (AK * 2);
    #pragma unroll
    for (int i = 0; i < 8; ++i) {
        float4 x = ((const float4*)p)[2 * i];
        float4 y = ((const float4*)p)[2 * i + 1];
        uint32_t h0, h1, h2, h3, l0, l1, l2, l3;
        split_pair(x.x, x.y, h0, l0);
        split_pair(x.z, x.w, h1, l1);
        split_pair(y.x, y.y, h2, l2);
        split_pair(y.z, y.w, h3, l3);
        *(uint4*)(dh + i * 16) = make_uint4(h0, h1, h2, h3);
        *(uint4*)(dl + i * 16) = make_uint4(l0, l1, l2, l3);
    }
}

// stage a 64x64 weight chunk (hi+lo) from global scratch, padded stride
__device__ __forceinline__ void stage_W(unsigned char* sm,
                                        const __nv_bfloat16* gh, const __nv_bfloat16* gl,
                                        int tid) {
    int row = tid >> 1, half = tid & 1;
    const uint4* sh = (const uint4*)(gh + row * 64 + half * 32);
    const uint4* sl = (const uint4*)(gl + row * 64 + half * 32);
    uint4* dh = (uint4*)(sm + SM_WH + row * (WK * 2) + half * 64);
    uint4* dl = (uint4*)(sm + SM_WL + row * (WK * 2) + half * 64);
    #pragma unroll
    for (int i = 0; i < 4; ++i) { dh[i] = sh[i]; dl[i] = sl[i]; }
}

// one K=64 chunk, bf16x3 split, per-k fragment caching.
// product order lo*hi -> hi*hi -> hi*lo keeps peak live fragments at 32 regs.
__device__ __forceinline__ void gemm_chunk(uint32_t aH, uint32_t aL,
                                           uint32_t wH, uint32_t wL,
                                           int m0, int lane, float acc[2][8][4]) {
    const uint32_t arow = (uint32_t)(lane & 15);
    const uint32_t acol = (uint32_t)((lane >> 4) * 8);
    #pragma unroll
    for (int k = 0; k < 4; ++k) {
        const uint32_t aoff = (arow * AK + k * 16 + acol) * 2;
        const uint32_t woff = (((uint32_t)(k * 16) + arow) * WK + acol) * 2;

        uint32_t a_lo[2][4], b_hi[4][4];
        #pragma unroll
        for (int mt = 0; mt < 2; ++mt)
            ldsm_x4(a_lo[mt], aL + aoff + (uint32_t)(m0 + mt * 16) * (AK * 2));
        #pragma unroll
        for (int nt = 0; nt < 4; ++nt)
            ldsm_x4_t(b_hi[nt], wH + woff + (uint32_t)(nt * 16) * 2);
        #pragma unroll
        for (int mt = 0; mt < 2; ++mt)
            #pragma unroll
            for (int nt = 0; nt < 8; ++nt)
                mma_bf16(acc[mt][nt], a_lo[mt], &b_hi[nt >> 1][(nt & 1) * 2]);

        uint32_t a_hi[2][4];
        #pragma unroll
        for (int mt = 0; mt < 2; ++mt)
            ldsm_x4(a_hi[mt], aH + aoff + (uint32_t)(m0 + mt * 16) * (AK * 2));
        #pragma unroll
        for (int mt = 0; mt < 2; ++mt)
            #pragma unroll
            for (int nt = 0; nt < 8; ++nt)
                mma_bf16(acc[mt][nt], a_hi[mt], &b_hi[nt >> 1][(nt & 1) * 2]);

        uint32_t b_lo[4][4];
        #pragma unroll
        for (int nt = 0; nt < 4; ++nt)
            ldsm_x4_t(b_lo[nt], wL + woff + (uint32_t)(nt * 16) * 2);
        #pragma unroll
        for (int mt = 0; mt < 2; ++mt)
            #pragma unroll
            for (int nt = 0; nt < 8; ++nt)
                mma_bf16(acc[mt][nt], a_hi[mt], &b_lo[nt >> 1][(nt & 1) * 2]);
    }
}

// ---------------- weight prep: bf16 split ----------------
__global__ void prep_weights(const float* __restrict__ W1, const float* __restrict__ W2) {
    int i = blockIdx.x * blockDim.x + threadIdx.x;
    if (i < 192 * 64) {
        float x = W1[i];
        __nv_bfloat16 h = __float2bfloat16_rn(x);
        g_W1h[i] = h;
        g_W1l[i] = __float2bfloat16_rn(x - __bfloat162float(h));
    } else if (i < 192 * 64 + 64 * 64) {
        int j = i - 192 * 64;
        float x = W2[j];
        __nv_bfloat16 h = __float2bfloat16_rn(x);
        g_W2h[j] = h;
        g_W2l[j] = __float2bfloat16_rn(x - __bfloat162float(h));
    }
}

// ---------------- main fused kernel ----------------
extern "C" __global__ void __launch_bounds__(THREADS, 4)
edge_update_hmma(const float* __restrict__ node,
                 const float* __restrict__ ef,
                 const int*   __restrict__ src,
                 const int*   __restrict__ dst,
                 const float* __restrict__ b1,
                 const float* __restrict__ b2,
                 const float* __restrict__ gamma,
                 const float* __restrict__ beta,
                 float*       __restrict__ out,
                 int E)
{
    extern __shared__ __align__(128) unsigned char sm[];
    const uint32_t smem_base = smem_u32(sm);
    const int tid  = threadIdx.x;
    const int lane = tid & 31;
    const int m0   = (tid >> 5) * 32;     // warp's edge-row base within tile
    const int base = blockIdx.x * TILE_E;

    if (tid < 64) {
        ((float*)(sm + SM_B1))[tid] = b1[tid];
        ((float*)(sm + SM_B2))[tid] = b2[tid];
        ((float*)(sm + SM_G))[tid]  = gamma[tid];
        ((float*)(sm + SM_BT))[tid] = beta[tid];
    }

    const int eg = base + tid;
    const int ec = (eg < E) ? eg : (E - 1);
    const float* srcRow = node + (size_t)src[ec] * 64;
    const float* dstRow = node + (size_t)dst[ec] * 64;
    const float* efRow  = ef   + (size_t)ec * 64;

    // warm L2 for the later chunks' gathers while chunk 0 runs
    prefetch_l2(dstRow);
    prefetch_l2(dstRow + 32);
    prefetch_l2(efRow);
    prefetch_l2(efRow + 32);

    float acc[2][8][4];
    #pragma unroll
    for (int mt = 0; mt < 2; ++mt)
        #pragma unroll
        for (int nt = 0; nt < 8; ++nt)
            #pragma unroll
            for (int j = 0; j < 4; ++j) acc[mt][nt][j] = 0.f;

    // ---------------- layer 1: 3 K-chunks of 64 ----------------
    #pragma unroll 1
    for (int c = 0; c < 3; ++c) {
        __syncthreads();   // prior chunk's ldmatrix reads complete before restage
        const float* p = (c == 0) ? srcRow : (c == 1) ? dstRow : efRow;
        stage_A_row(sm, tid, p);
        stage_W(sm, g_W1h + c * 4096, g_W1l + c * 4096, tid);
        __syncthreads();
        gemm_chunk(smem_base + SM_AH, smem_base + SM_AL,
                   smem_base + SM_WH, smem_base + SM_WL, m0, lane, acc);
    }

    // ---------------- epilogue 1: bias + SiLU, restage h as bf16 hi/lo ----------------
    __syncthreads();            // everyone done reading W1 chunk & own A rows
    stage_W(sm, g_W2h, g_W2l, tid);
    {
        const float* b1s = (const float*)(sm + SM_B1);
        #pragma unroll
        for (int mt = 0; mt < 2; ++mt)
            #pragma unroll
            for (int nt = 0; nt < 8; ++nt) {
                int col = nt * 8 + (lane & 3) * 2;
                float bb0 = b1s[col], bb1 = b1s[col + 1];
                int r0 = m0 + mt * 16 + (lane >> 2);
                int r1 = r0 + 8;
                float h00 = silu_f(acc[mt][nt][0] + bb0);
                float h01 = silu_f(acc[mt][nt][1] + bb1);
                float h10 = silu_f(acc[mt][nt][2] + bb0);
                float h11 = silu_f(acc[mt][nt][3] + bb1);
                uint32_t hi, lo;
                split_pair(h00, h01, hi, lo);
                *(uint32_t*)(sm + SM_AH + r0 * (AK * 2) + col * 2) = hi;
                *(uint32_t*)(sm + SM_AL + r0 * (AK * 2) + col * 2) = lo;
                split_pair(h10, h11, hi, lo);
                *(uint32_t*)(sm + SM_AH + r1 * (AK * 2) + col * 2) = hi;
                *(uint32_t*)(sm + SM_AL + r1 * (AK * 2) + col * 2) = lo;
            }
    }
    #pragma unroll
    for (int mt = 0; mt < 2; ++mt)
        #pragma unroll
        for (int nt = 0; nt < 8; ++nt)
            #pragma unroll
            for (int j = 0; j < 4; ++j) acc[mt][nt][j] = 0.f;
    __syncthreads();

    // ---------------- layer 2: K=64 ----------------
    gemm_chunk(smem_base + SM_AH, smem_base + SM_AL,
               smem_base + SM_WH, smem_base + SM_WL, m0, lane, acc);

    // ---------------- epilogue 2: residual + LayerNorm on fragments ----------------
    {
        const float* b2s = (const float*)(sm + SM_B2);
        const float* gs  = (const float*)(sm + SM_G);
        const float* bts = (const float*)(sm + SM_BT);
        #pragma unroll
        for (int mt = 0; mt < 2; ++mt) {
            #pragma unroll
            for (int half = 0; half < 2; ++half) {
                int r = m0 + mt * 16 + (lane >> 2) + half * 8;
                int e = base + r;
                int eclamp = (e < E) ? e : (E - 1);
                const float* efr = ef + (size_t)eclamp * 64;
                float o[16];
                float s = 0.f, sq = 0.f;
                #pragma unroll
                for (int nt = 0; nt < 8; ++nt) {
                    int col = nt * 8 + (lane & 3) * 2;
                    float2 f = *(const float2*)(efr + col);
                    float v0 = f.x + silu_f(acc[mt][nt][half * 2 + 0] + b2s[col]);
                    float v1 = f.y + silu_f(acc[mt][nt][half * 2 + 1] + b2s[col + 1]);
                    o[nt * 2] = v0;
                    o[nt * 2 + 1] = v1;
                    s += v0 + v1;
                    sq += v0 * v0 + v1 * v1;
                }
                s  += __shfl_xor_sync(0xffffffffu, s, 1);
                sq += __shfl_xor_sync(0xffffffffu, sq, 1);
                s  += __shfl_xor_sync(0xffffffffu, s, 2);
                sq += __shfl_xor_sync(0xffffffffu, sq, 2);
                float mu  = s * (1.0f / 64.0f);
                float var = sq * (1.0f / 64.0f) - mu * mu;
                float rs  = rsqrtf(var + 1e-5f);
                if (e < E) {
                    float* op = out + (size_t)e * 64;
                    #pragma unroll
                    for (int nt = 0; nt < 8; ++nt) {
                        int col = nt * 8 + (lane & 3) * 2;
                        float2 w;
                        w.x = (o[nt * 2]     - mu) * rs * gs[col]     + bts[col];
                        w.y = (o[nt * 2 + 1] - mu) * rs * gs[col + 1] + bts[col + 1];
                        *(float2*)(op + col) = w;
                    }
                }
            }
        }
    }
}

extern "C" void kernel_launch(void* const* d_in, const int* in_sizes, int n_in,
                              void* d_out, int out_size)
{
    const float* node  = (const float*)d_in[0];
    const float* ef    = (const float*)d_in[1];
    const int*   src   = (const int*)d_in[2];
    const int*   dst   = (const int*)d_in[3];
    const float* W1    = (const float*)d_in[4];
    const float* b1    = (const float*)d_in[5];
    const float* W2    = (const float*)d_in[6];
    const float* b2    = (const float*)d_in[7];
    const float* gamma = (const float*)d_in[8];
    const float* beta  = (const float*)d_in[9];
    float* out = (float*)d_out;

    const int E = in_sizes[2];
    const int nTiles = (E + TILE_E - 1) / TILE_E;

    prep_weights<<<64, 256>>>(W1, W2);

    cudaFuncSetAttribute(edge_update_hmma,
                         cudaFuncAttributeMaxDynamicSharedMemorySize, SMEM_BYTES);
    edge_update_hmma<<<nTiles, THREADS, SMEM_BYTES>>>(
        node, ef, src, dst, b1, b2, gamma, beta, out, E);
}

// round 10
// speedup vs baseline: 3.7354x; 1.2902x over previous
#include <cuda_runtime.h>
#include <cuda_bf16.h>
#include <cstdint>

#define THREADS 128
#define TILE_E  128
#define AK 72            // padded row stride (bf16 elems) for A/h tiles
#define WK 72            // padded row stride for weight tiles

// ---------------- shared memory byte offsets ----------------
#define SM_B1 0
#define SM_B2 256
#define SM_G  512
#define SM_BT 768
#define SM_AH 1024
#define SM_AL (SM_AH + 128*AK*2)      // 19456
#define SM_WH (SM_AL + 128*AK*2)      // 37888
#define SM_WL (SM_WH + 64*WK*2)       // 47104
#define SMEM_BYTES (SM_WL + 64*WK*2)  // 56320  (x4 CTAs = 225280 <= 227328)

// bf16-split weights, natural [k][n] layout
static __device__ __nv_bfloat16 g_W1h[192 * 64];
static __device__ __nv_bfloat16 g_W1l[192 * 64];
static __device__ __nv_bfloat16 g_W2h[64 * 64];
static __device__ __nv_bfloat16 g_W2l[64 * 64];

// ---------------- ptx helpers ----------------
__device__ __forceinline__ uint32_t smem_u32(const void* p) {
    uint32_t a;
    asm("{ .reg .u64 t; cvta.to.shared.u64 t, %1; cvt.u32.u64 %0, t; }" : "=r"(a) : "l"(p));
    return a;
}
__device__ __forceinline__ void ldsm_x4(uint32_t* r, uint32_t addr) {
    asm volatile("ldmatrix.sync.aligned.m8n8.x4.shared.b16 {%0,%1,%2,%3}, [%4];"
                 : "=r"(r[0]), "=r"(r[1]), "=r"(r[2]), "=r"(r[3]) : "r"(addr));
}
__device__ __forceinline__ void ldsm_x4_t(uint32_t* r, uint32_t addr) {
    asm volatile("ldmatrix.sync.aligned.m8n8.x4.trans.shared.b16 {%0,%1,%2,%3}, [%4];"
                 : "=r"(r[0]), "=r"(r[1]), "=r"(r[2]), "=r"(r[3]) : "r"(addr));
}
__device__ __forceinline__ void mma_bf16(float* c, const uint32_t* a, const uint32_t* b) {
    asm volatile(
        "mma.sync.aligned.m16n8k16.row.col.f32.bf16.bf16.f32 "
        "{%0,%1,%2,%3}, {%4,%5,%6,%7}, {%8,%9}, {%0,%1,%2,%3};"
        : "+f"(c[0]), "+f"(c[1]), "+f"(c[2]), "+f"(c[3])
        : "r"(a[0]), "r"(a[1]), "r"(a[2]), "r"(a[3]), "r"(b[0]), "r"(b[1]));
}
__device__ __forceinline__ void prefetch_l2(const void* p) {
    asm volatile("prefetch.global.L2 [%0];" :: "l"(p));
}

// ---------------- math helpers ----------------
__device__ __forceinline__ float silu_f(float x) { return x / (1.0f + __expf(-x)); }

__device__ __forceinline__ void split_pair(float a, float b, uint32_t& hi, uint32_t& lo) {
    __nv_bfloat162 h = __floats2bfloat162_rn(a, b);
    float la = a - __low2float(h);
    float lb = b - __high2float(h);
    __nv_bfloat162 l = __floats2bfloat162_rn(la, lb);
    hi = *(uint32_t*)&h;
    lo = *(uint32_t*)&l;
}

// cooperative gather+split staging: 16 lanes cover one 256B row contiguously,
// 2 rows per LDG.128 warp-instruction (4 lines vs 32 with per-thread rows).
// idx == nullptr -> identity (edge_feats rows); else gather node rows.
__device__ __forceinline__ void stage_A_coop(unsigned char* sm, int warp, int lane,
                                             const float* __restrict__ basePtr,
                                             const int*   __restrict__ idx,
                                             int baseEdge, int E) {
    const int lane16 = lane & 15;
    const int rsel   = lane >> 4;
    #pragma unroll
    for (int i = 0; i < 16; ++i) {
        int row = warp * 32 + i * 2 + rsel;
        int e   = baseEdge + row;
        int ec  = (e < E) ? e : (E - 1);
        int r   = idx ? idx[ec] : ec;
        float4 v = ((const float4*)(basePtr + (size_t)r * 64))[lane16];
        uint32_t h0, h1, l0, l1;
        split_pair(v.x, v.y, h0, l0);
        split_pair(v.z, v.w, h1, l1);
        uint32_t off = (uint32_t)row * (AK * 2) + (uint32_t)lane16 * 8;
        *(uint2*)(sm + SM_AH + off) = make_uint2(h0, h1);
        *(uint2*)(sm + SM_AL + off) = make_uint2(l0, l1);
    }
}

// stage a 64x64 weight chunk (hi+lo) from global scratch, padded stride
__device__ __forceinline__ void stage_W(unsigned char* sm,
                                        const __nv_bfloat16* gh, const __nv_bfloat16* gl,
                                        int tid) {
    int row = tid >> 1, half = tid & 1;
    const uint4* sh = (const uint4*)(gh + row * 64 + half * 32);
    const uint4* sl = (const uint4*)(gl + row * 64 + half * 32);
    uint4* dh = (uint4*)(sm + SM_WH + row * (WK * 2) + half * 64);
    uint4* dl = (uint4*)(sm + SM_WL + row * (WK * 2) + half * 64);
    #pragma unroll
    for (int i = 0; i < 4; ++i) { dh[i] = sh[i]; dl[i] = sl[i]; }
}

// one K=64 chunk, bf16x3 split, per-k fragment caching.
// product order lo*hi -> hi*hi -> hi*lo keeps peak live fragments at 32 regs.
__device__ __forceinline__ void gemm_chunk(uint32_t aH, uint32_t aL,
                                           uint32_t wH, uint32_t wL,
                                           int m0, int lane, float acc[2][8][4]) {
    const uint32_t arow = (uint32_t)(lane & 15);
    const uint32_t acol = (uint32_t)((lane >> 4) * 8);
    #pragma unroll
    for (int k = 0; k < 4; ++k) {
        const uint32_t aoff = (arow * AK + k * 16 + acol) * 2;
        const uint32_t woff = (((uint32_t)(k * 16) + arow) * WK + acol) * 2;

        uint32_t a_lo[2][4], b_hi[4][4];
        #pragma unroll
        for (int mt = 0; mt < 2; ++mt)
            ldsm_x4(a_lo[mt], aL + aoff + (uint32_t)(m0 + mt * 16) * (AK * 2));
        #pragma unroll
        for (int nt = 0; nt < 4; ++nt)
            ldsm_x4_t(b_hi[nt], wH + woff + (uint32_t)(nt * 16) * 2);
        #pragma unroll
        for (int mt = 0; mt < 2; ++mt)
            #pragma unroll
            for (int nt = 0; nt < 8; ++nt)
                mma_bf16(acc[mt][nt], a_lo[mt], &b_hi[nt >> 1][(nt & 1) * 2]);

        uint32_t a_hi[2][4];
        #pragma unroll
        for (int mt = 0; mt < 2; ++mt)
            ldsm_x4(a_hi[mt], aH + aoff + (uint32_t)(m0 + mt * 16) * (AK * 2));
        #pragma unroll
        for (int mt = 0; mt < 2; ++mt)
            #pragma unroll
            for (int nt = 0; nt < 8; ++nt)
                mma_bf16(acc[mt][nt], a_hi[mt], &b_hi[nt >> 1][(nt & 1) * 2]);

        uint32_t b_lo[4][4];
        #pragma unroll
        for (int nt = 0; nt < 4; ++nt)
            ldsm_x4_t(b_lo[nt], wL + woff + (uint32_t)(nt * 16) * 2);
        #pragma unroll
        for (int mt = 0; mt < 2; ++mt)
            #pragma unroll
            for (int nt = 0; nt < 8; ++nt)
                mma_bf16(acc[mt][nt], a_hi[mt], &b_lo[nt >> 1][(nt & 1) * 2]);
    }
}

// ---------------- weight prep: bf16 split ----------------
__global__ void prep_weights(const float* __restrict__ W1, const float* __restrict__ W2) {
    int i = blockIdx.x * blockDim.x + threadIdx.x;
    if (i < 192 * 64) {
        float x = W1[i];
        __nv_bfloat16 h = __float2bfloat16_rn(x);
        g_W1h[i] = h;
        g_W1l[i] = __float2bfloat16_rn(x - __bfloat162float(h));
    } else if (i < 192 * 64 + 64 * 64) {
        int j = i - 192 * 64;
        float x = W2[j];
        __nv_bfloat16 h = __float2bfloat16_rn(x);
        g_W2h[j] = h;
        g_W2l[j] = __float2bfloat16_rn(x - __bfloat162float(h));
    }
}

// ---------------- main fused kernel ----------------
extern "C" __global__ void __launch_bounds__(THREADS, 4)
edge_update_hmma(const float* __restrict__ node,
                 const float* __restrict__ ef,
                 const int*   __restrict__ src,
                 const int*   __restrict__ dst,
                 const float* __restrict__ b1,
                 const float* __restrict__ b2,
                 const float* __restrict__ gamma,
                 const float* __restrict__ beta,
                 float*       __restrict__ out,
                 int E)
{
    extern __shared__ __align__(128) unsigned char sm[];
    const uint32_t smem_base = smem_u32(sm);
    const int tid  = threadIdx.x;
    const int lane = tid & 31;
    const int warp = tid >> 5;
    const int m0   = warp * 32;           // warp's edge-row base within tile
    const int base = blockIdx.x * TILE_E;

    if (tid < 64) {
        ((float*)(sm + SM_B1))[tid] = b1[tid];
        ((float*)(sm + SM_B2))[tid] = b2[tid];
        ((float*)(sm + SM_G))[tid]  = gamma[tid];
        ((float*)(sm + SM_BT))[tid] = beta[tid];
    }

    // L2 warm for later chunks (owner-thread granularity is fine for prefetch)
    {
        const int eg = base + tid;
        const int ec = (eg < E) ? eg : (E - 1);
        prefetch_l2(node + (size_t)dst[ec] * 64);
        prefetch_l2(node + (size_t)dst[ec] * 64 + 32);
        prefetch_l2(ef + (size_t)ec * 64);
        prefetch_l2(ef + (size_t)ec * 64 + 32);
    }

    float acc[2][8][4];
    #pragma unroll
    for (int mt = 0; mt < 2; ++mt)
        #pragma unroll
        for (int nt = 0; nt < 8; ++nt)
            #pragma unroll
            for (int j = 0; j < 4; ++j) acc[mt][nt][j] = 0.f;

    // ---------------- layer 1: 3 K-chunks of 64 ----------------
    #pragma unroll 1
    for (int c = 0; c < 3; ++c) {
        __syncthreads();   // prior chunk's ldmatrix reads complete before restage
        if (c == 0)      stage_A_coop(sm, warp, lane, node, src, base, E);
        else if (c == 1) stage_A_coop(sm, warp, lane, node, dst, base, E);
        else             stage_A_coop(sm, warp, lane, ef, (const int*)nullptr, base, E);
        stage_W(sm, g_W1h + c * 4096, g_W1l + c * 4096, tid);
        __syncthreads();
        gemm_chunk(smem_base + SM_AH, smem_base + SM_AL,
                   smem_base + SM_WH, smem_base + SM_WL, m0, lane, acc);
    }

    // ---------------- epilogue 1: bias + SiLU, restage h as bf16 hi/lo ----------------
    __syncthreads();            // everyone done reading W1 chunk & A tiles
    stage_W(sm, g_W2h, g_W2l, tid);
    {
        const float* b1s = (const float*)(sm + SM_B1);
        #pragma unroll
        for (int mt = 0; mt < 2; ++mt)
            #pragma unroll
            for (int nt = 0; nt < 8; ++nt) {
                int col = nt * 8 + (lane & 3) * 2;
                float bb0 = b1s[col], bb1 = b1s[col + 1];
                int r0 = m0 + mt * 16 + (lane >> 2);
                int r1 = r0 + 8;
                float h00 = silu_f(acc[mt][nt][0] + bb0);
                float h01 = silu_f(acc[mt][nt][1] + bb1);
                float h10 = silu_f(acc[mt][nt][2] + bb0);
                float h11 = silu_f(acc[mt][nt][3] + bb1);
                uint32_t hi, lo;
                split_pair(h00, h01, hi, lo);
                *(uint32_t*)(sm + SM_AH + r0 * (AK * 2) + col * 2) = hi;
                *(uint32_t*)(sm + SM_AL + r0 * (AK * 2) + col * 2) = lo;
                split_pair(h10, h11, hi, lo);
                *(uint32_t*)(sm + SM_AH + r1 * (AK * 2) + col * 2) = hi;
                *(uint32_t*)(sm + SM_AL + r1 * (AK * 2) + col * 2) = lo;
            }
    }
    #pragma unroll
    for (int mt = 0; mt < 2; ++mt)
        #pragma unroll
        for (int nt = 0; nt < 8; ++nt)
            #pragma unroll
            for (int j = 0; j < 4; ++j) acc[mt][nt][j] = 0.f;
    __syncthreads();

    // ---------------- layer 2: K=64 ----------------
    gemm_chunk(smem_base + SM_AH, smem_base + SM_AL,
               smem_base + SM_WH, smem_base + SM_WL, m0, lane, acc);

    // ---------------- epilogue 2: residual + LayerNorm on fragments ----------------
    {
        const float* b2s = (const float*)(sm + SM_B2);
        const float* gs  = (const float*)(sm + SM_G);
        const float* bts = (const float*)(sm + SM_BT);
        #pragma unroll
        for (int mt = 0; mt < 2; ++mt) {
            #pragma unroll
            for (int half = 0; half < 2; ++half) {
                int r = m0 + mt * 16 + (lane >> 2) + half * 8;
                int e = base + r;
                int eclamp = (e < E) ? e : (E - 1);
                const float* efr = ef + (size_t)eclamp * 64;
                float o[16];
                float s = 0.f, sq = 0.f;
                #pragma unroll
                for (int nt = 0; nt < 8; ++nt) {
                    int col = nt * 8 + (lane & 3) * 2;
                    float2 f = *(const float2*)(efr + col);
                    float v0 = f.x + silu_f(acc[mt][nt][half * 2 + 0] + b2s[col]);
                    float v1 = f.y + silu_f(acc[mt][nt][half * 2 + 1] + b2s[col + 1]);
                    o[nt * 2] = v0;
                    o[nt * 2 + 1] = v1;
                    s += v0 + v1;
                    sq += v0 * v0 + v1 * v1;
                }
                s  += __shfl_xor_sync(0xffffffffu, s, 1);
                sq += __shfl_xor_sync(0xffffffffu, sq, 1);
                s  += __shfl_xor_sync(0xffffffffu, s, 2);
                sq += __shfl_xor_sync(0xffffffffu, sq, 2);
                float mu  = s * (1.0f / 64.0f);
                float var = sq * (1.0f / 64.0f) - mu * mu;
                float rs  = rsqrtf(var + 1e-5f);
                if (e < E) {
                    float* op = out + (size_t)e * 64;
                    #pragma unroll
                    for (int nt = 0; nt < 8; ++nt) {
                        int col = nt * 8 + (lane & 3) * 2;
                        float2 w;
                        w.x = (o[nt * 2]     - mu) * rs * gs[col]     + bts[col];
                        w.y = (o[nt * 2 + 1] - mu) * rs * gs[col + 1] + bts[col + 1];
                        *(float2*)(op + col) = w;
                    }
                }
            }
        }
    }
}

extern "C" void kernel_launch(void* const* d_in, const int* in_sizes, int n_in,
                              void* d_out, int out_size)
{
    const float* node  = (const float*)d_in[0];
    const float* ef    = (const float*)d_in[1];
    const int*   src   = (const int*)d_in[2];
    const int*   dst   = (const int*)d_in[3];
    const float* W1    = (const float*)d_in[4];
    const float* b1    = (const float*)d_in[5];
    const float* W2    = (const float*)d_in[6];
    const float* b2    = (const float*)d_in[7];
    const float* gamma = (const float*)d_in[8];
    const float* beta  = (const float*)d_in[9];
    float* out = (float*)d_out;

    const int E = in_sizes[2];
    const int nTiles = (E + TILE_E - 1) / TILE_E;

    prep_weights<<<64, 256>>>(W1, W2);

    cudaFuncSetAttribute(edge_update_hmma,
                         cudaFuncAttributeMaxDynamicSharedMemorySize, SMEM_BYTES);
    edge_update_hmma<<<nTiles, THREADS, SMEM_BYTES>>>(
        node, ef, src, dst, b1, b2, gamma, beta, out, E);
}